// round 8
// baseline (speedup 1.0000x reference)
#include <cuda_runtime.h>
#include <cuda_fp16.h>

#define BB 8
#define TT 512
#define DD 64
#define TILE 64
#define NT (TT / TILE)               // 8 tiles per dim
#define NPAIR (NT * (NT + 1) / 2)    // 36 upper-tri tile pairs
#define TSTR 66                       // transposed [d][row] stride (floats)

// sqrt(log2(e)): pre-scale x so exp(-(dx)^2) = ex2(-(s*dx)^2)
#define SQRT_LOG2E 1.2011224087864498f

typedef unsigned long long u64;

__device__ float g_v[BB * TT * DD];   // scratch: v = x @ W^T + b (512 KB)

// ---- f32x2 packed helpers (sm_103a) --------------------------------------
__device__ __forceinline__ u64 pack2(float lo, float hi) {
    u64 r; asm("mov.b64 %0, {%1, %2};" : "=l"(r) : "f"(lo), "f"(hi)); return r;
}
__device__ __forceinline__ void unpack2(u64 v, float& lo, float& hi) {
    asm("mov.b64 {%0, %1}, %2;" : "=f"(lo), "=f"(hi) : "l"(v));
}
__device__ __forceinline__ u64 add2(u64 a, u64 b) {
    u64 r; asm("add.rn.f32x2 %0, %1, %2;" : "=l"(r) : "l"(a), "l"(b)); return r;
}
__device__ __forceinline__ u64 mul2(u64 a, u64 b) {
    u64 r; asm("mul.rn.f32x2 %0, %1, %2;" : "=l"(r) : "l"(a), "l"(b)); return r;
}
__device__ __forceinline__ u64 fma2(u64 a, u64 b, u64 c) {
    u64 r; asm("fma.rn.f32x2 %0, %1, %2, %3;" : "=l"(r) : "l"(a), "l"(b), "l"(c)); return r;
}

// Packed dual exp: given {t0,t1} (f32, t>=0), return {exp2(-t0), exp2(-t1)}
// as two f32. One cvt-pack (F2FP), one LOP3 (packed f16x2 negate), ONE
// MUFU.EX2 (f16x2 = 2 exps per MUFU slot), two F2F back-converts.
__device__ __forceinline__ void ex2neg_pair(float t0, float t1,
                                            float& e0, float& e1) {
    unsigned h;
    // PTX: cvt.rn.f16x2.f32 d, a, b -> upper = cvt(a), lower = cvt(b)
    asm("cvt.rn.f16x2.f32 %0, %1, %2;" : "=r"(h) : "f"(t1), "f"(t0));
    h ^= 0x80008000u;                    // negate both halves (ALU)
    unsigned eh;
    asm("ex2.approx.f16x2 %0, %1;" : "=r"(eh) : "r"(h));
    asm("{\n\t"
        ".reg .b16 lo, hi;\n\t"
        "mov.b32 {lo, hi}, %2;\n\t"
        "cvt.f32.f16 %0, lo;\n\t"
        "cvt.f32.f16 %1, hi;\n\t"
        "}" : "=f"(e0), "=f"(e1) : "r"(eh));
}

// ---------------------------------------------------------------------------
// Kernel 1: v[b,t,e] = sum_d x[b,t,d] * W[e,d] + bias[e]
// 128 blocks x 256 threads, 32 rows/block; f32x2 FMAs.
// ---------------------------------------------------------------------------
#define WSTR 68
__global__ __launch_bounds__(256)
void v_kernel(const float* __restrict__ x, const float* __restrict__ W,
              const float* __restrict__ bias) {
    __shared__ float sWT[DD * WSTR];     // sWT[d*68 + e] = W[e*64 + d]
    __shared__ float sX[32 * DD];

    int tid = threadIdx.x;
    int row0 = blockIdx.x * 32;

    for (int k = tid; k < DD * DD; k += 256) {
        int e = k >> 6, d = k & 63;
        sWT[d * WSTR + e] = W[k];
    }
    for (int k = tid; k < 32 * DD; k += 256)
        sX[k] = x[row0 * DD + k];
    __syncthreads();

    int eg = tid & 15;                   // e = 4*eg .. 4*eg+3
    int rs = tid >> 4;                   // rows rs, rs+16
    float4 b4 = *(const float4*)&bias[4 * eg];
    u64 acc0a = pack2(b4.x, b4.y), acc0b = pack2(b4.z, b4.w);
    u64 acc1a = acc0a, acc1b = acc0b;

#pragma unroll 8
    for (int d = 0; d < DD; d++) {
        const float* wp = &sWT[d * WSTR + 4 * eg];
        u64 wA = *(const u64*)&wp[0];
        u64 wB = *(const u64*)&wp[2];
        float x0 = sX[rs * DD + d];
        float x1 = sX[(rs + 16) * DD + d];
        u64 x0p = pack2(x0, x0), x1p = pack2(x1, x1);
        acc0a = fma2(x0p, wA, acc0a);
        acc0b = fma2(x0p, wB, acc0b);
        acc1a = fma2(x1p, wA, acc1a);
        acc1b = fma2(x1p, wB, acc1b);
    }
    float o0, o1, o2, o3;
    unpack2(acc0a, o0, o1); unpack2(acc0b, o2, o3);
    *(float4*)&g_v[(row0 + rs) * DD + 4 * eg] = make_float4(o0, o1, o2, o3);
    unpack2(acc1a, o0, o1); unpack2(acc1b, o2, o3);
    *(float4*)&g_v[(row0 + rs + 16) * DD + 4 * eg] = make_float4(o0, o1, o2, o3);
}

// ---------------------------------------------------------------------------
// Kernel 2: pairwise RBF with (i,j) symmetry. Block = (b, upper-tri 64x64
// tile pair), 256 threads, 4x4 elems/thread, 2 CTAs/SM. R4 structure with
// the exp path swapped to f16x2 MUFU (2 exps / MUFU slot -> MUFU floor
// halved). Transposed [d][row] smem: conflict-free inner LDS. j staged
// negated: diff = one add2.
// ---------------------------------------------------------------------------
__global__ __launch_bounds__(256, 2)
void rbf_kernel(const float* __restrict__ x, float* __restrict__ out) {
    extern __shared__ float smem[];
    float* XI  = smem;                   // +s*xi   [d*66 + row]
    float* NXJ = XI  + DD * TSTR;        // -s*xj
    float* VI  = NXJ + DD * TSTR;
    float* VJ  = VI  + DD * TSTR;

    int b = blockIdx.y;
    int p = blockIdx.x;
    int ti = 0, rem = p;
    while (rem >= NT - ti) { rem -= NT - ti; ti++; }
    int tj = ti + rem;
    int i0 = ti * TILE, j0 = tj * TILE;

    int tid = threadIdx.x;
    const float* xb = x + b * TT * DD;
    const float* vb = g_v + b * TT * DD;

#pragma unroll
    for (int k = 0; k < 16; k++) {
        int idx = tid + k * 256;
        int r = idx >> 6, d = idx & 63;
        int sa = d * TSTR + r;
        XI[sa]  =  SQRT_LOG2E * xb[i0 * DD + idx];
        NXJ[sa] = -SQRT_LOG2E * xb[j0 * DD + idx];
        VI[sa]  = vb[i0 * DD + idx];
        VJ[sa]  = vb[j0 * DD + idx];
    }
    __syncthreads();

    int tx = tid & 15, ty = tid >> 4;

    u64 den[4][2], ni[4][2], nj[4][2];
#pragma unroll
    for (int r = 0; r < 4; r++)
#pragma unroll
        for (int c = 0; c < 2; c++) { den[r][c] = 0ULL; ni[r][c] = 0ULL; nj[r][c] = 0ULL; }

#pragma unroll 2
    for (int d = 0; d < DD; d++) {
        const float* XId  = XI  + d * TSTR;
        const float* VId  = VI  + d * TSTR;
        const float* NXJd = NXJ + d * TSTR;
        const float* VJd  = VJ  + d * TSTR;

        float2 fiA = *(const float2*)&XId[2 * ty];        // broadcast
        float2 fiB = *(const float2*)&XId[2 * ty + 32];
        float2 fvA = *(const float2*)&VId[2 * ty];
        float2 fvB = *(const float2*)&VId[2 * ty + 32];
        u64 njc[2], jvc[2];
        njc[0] = *(const u64*)&NXJd[2 * tx];              // spread, conflict-free
        njc[1] = *(const u64*)&NXJd[2 * tx + 32];
        jvc[0] = *(const u64*)&VJd[2 * tx];
        jvc[1] = *(const u64*)&VJd[2 * tx + 32];

        float fi[4] = {fiA.x, fiA.y, fiB.x, fiB.y};
        float fv[4] = {fvA.x, fvA.y, fvB.x, fvB.y};

#pragma unroll
        for (int r = 0; r < 4; r++) {
            u64 fid = pack2(fi[r], fi[r]);
            u64 fvd = pack2(fv[r], fv[r]);
#pragma unroll
            for (int c = 0; c < 2; c++) {
                u64 a2 = add2(fid, njc[c]);      // s*(xi - xj), 2 elems
                u64 t2 = mul2(a2, a2);           // +t = (s*dd)^2
                float t0, t1; unpack2(t2, t0, t1);
                float e0, e1;
                ex2neg_pair(t0, t1, e0, e1);     // ONE MUFU for both exps
                u64 e2 = pack2(e0, e1);
                den[r][c] = add2(den[r][c], e2);
                ni[r][c]  = fma2(e2, fvd, ni[r][c]);
                nj[r][c]  = fma2(e2, jvc[c], nj[r][c]);
            }
        }
    }

    float* ob = out + (size_t)b * TT * TT;
    int rowOf[4] = {2 * ty, 2 * ty + 1, 2 * ty + 32, 2 * ty + 33};

    float oi[4][2][2], oj[4][2][2];
#pragma unroll
    for (int r = 0; r < 4; r++)
#pragma unroll
        for (int c = 0; c < 2; c++) {
            float d0, d1, n0, n1, q0, q1;
            unpack2(den[r][c], d0, d1);
            unpack2(ni[r][c],  n0, n1);
            unpack2(nj[r][c],  q0, q1);
            float rc0, rc1;
            asm("rcp.approx.ftz.f32 %0, %1;" : "=f"(rc0) : "f"(d0));
            asm("rcp.approx.ftz.f32 %0, %1;" : "=f"(rc1) : "f"(d1));
            oi[r][c][0] = n0 * rc0; oi[r][c][1] = n1 * rc1;
            oj[r][c][0] = q0 * rc0; oj[r][c][1] = q1 * rc1;
        }

    // main writes: float2, coalesced across tx
#pragma unroll
    for (int r = 0; r < 4; r++) {
        int gi = i0 + rowOf[r];
#pragma unroll
        for (int c = 0; c < 2; c++) {
            float2 w = make_float2(oi[r][c][0], oi[r][c][1]);
            *(float2*)&ob[(size_t)gi * TT + j0 + 2 * tx + 32 * c] = w;
        }
    }

    if (ti != tj) {
        // mirror: out[b, gj, gi..gi+1]
#pragma unroll
        for (int c = 0; c < 2; c++) {
#pragma unroll
            for (int e = 0; e < 2; e++) {
                int gj = j0 + 2 * tx + 32 * c + e;
                float2 w0 = make_float2(oj[0][c][e], oj[1][c][e]);
                float2 w1 = make_float2(oj[2][c][e], oj[3][c][e]);
                *(float2*)&ob[(size_t)gj * TT + i0 + 2 * ty]      = w0;
                *(float2*)&ob[(size_t)gj * TT + i0 + 2 * ty + 32] = w1;
            }
        }
    }
}

extern "C" void kernel_launch(void* const* d_in, const int* in_sizes, int n_in,
                              void* d_out, int out_size) {
    const float* x = (const float*)d_in[0];    // (8,512,64)
    const float* W = (const float*)d_in[1];    // (64,64)
    const float* bias = (const float*)d_in[2]; // (64,)
    float* out = (float*)d_out;                // (8,512,512)

    static bool attr_set = false;
    size_t smem_bytes = 4 * DD * TSTR * sizeof(float);   // 67584
    if (!attr_set) {
        cudaFuncSetAttribute(rbf_kernel,
                             cudaFuncAttributeMaxDynamicSharedMemorySize,
                             (int)smem_bytes);
        attr_set = true;
    }

    v_kernel<<<(BB * TT) / 32, 256>>>(x, W, bias);
    rbf_kernel<<<dim3(NPAIR, BB), 256, smem_bytes>>>(x, out);
}

// round 9
// speedup vs baseline: 1.1329x; 1.1329x over previous
#include <cuda_runtime.h>
#include <cuda_fp16.h>

#define BB 8
#define TT 512
#define DD 64
#define TILE 64
#define NT (TT / TILE)               // 8 tiles per dim
#define NPAIR (NT * (NT + 1) / 2)    // 36 upper-tri tile pairs
#define HSTR 66                       // transposed [d][row] stride (halves)

// sqrt(log2(e)): pre-scale x so exp(-(dx)^2) = ex2(-(s*dx)^2)
#define SQRT_LOG2E 1.2011224087864498f

typedef unsigned long long u64;
typedef __half2 h2;

__device__ float g_v[BB * TT * DD];   // scratch: v = x @ W^T + b (512 KB)

// ---- f32x2 packed helpers (v_kernel) --------------------------------------
__device__ __forceinline__ u64 pack2(float lo, float hi) {
    u64 r; asm("mov.b64 %0, {%1, %2};" : "=l"(r) : "f"(lo), "f"(hi)); return r;
}
__device__ __forceinline__ void unpack2(u64 v, float& lo, float& hi) {
    asm("mov.b64 {%0, %1}, %2;" : "=f"(lo), "=f"(hi) : "l"(v));
}
__device__ __forceinline__ u64 fma2(u64 a, u64 b, u64 c) {
    u64 r; asm("fma.rn.f32x2 %0, %1, %2, %3;" : "=l"(r) : "l"(a), "l"(b), "l"(c)); return r;
}

// ---- f16x2 helpers ---------------------------------------------------------
__device__ __forceinline__ h2 h2neg(h2 a) {
    unsigned u; asm("mov.b32 %0, %1;" : "=r"(u) : "r"(*(unsigned*)&a));
    u ^= 0x80008000u;
    return *(h2*)&u;
}
__device__ __forceinline__ h2 hex2(h2 a) {
    unsigned r, u = *(unsigned*)&a;
    asm("ex2.approx.f16x2 %0, %1;" : "=r"(r) : "r"(u));
    return *(h2*)&r;
}

// ---------------------------------------------------------------------------
// Kernel 1: v[b,t,e] = sum_d x[b,t,d] * W[e,d] + bias[e]
// 128 blocks x 256 threads, 32 rows/block; f32x2 FMAs.
// ---------------------------------------------------------------------------
#define WSTR 68
__global__ __launch_bounds__(256)
void v_kernel(const float* __restrict__ x, const float* __restrict__ W,
              const float* __restrict__ bias) {
    __shared__ float sWT[DD * WSTR];     // sWT[d*68 + e] = W[e*64 + d]
    __shared__ float sX[32 * DD];

    int tid = threadIdx.x;
    int row0 = blockIdx.x * 32;

    for (int k = tid; k < DD * DD; k += 256) {
        int e = k >> 6, d = k & 63;
        sWT[d * WSTR + e] = W[k];
    }
    for (int k = tid; k < 32 * DD; k += 256)
        sX[k] = x[row0 * DD + k];
    __syncthreads();

    int eg = tid & 15;
    int rs = tid >> 4;
    float4 b4 = *(const float4*)&bias[4 * eg];
    u64 acc0a = pack2(b4.x, b4.y), acc0b = pack2(b4.z, b4.w);
    u64 acc1a = acc0a, acc1b = acc0b;

#pragma unroll 8
    for (int d = 0; d < DD; d++) {
        const float* wp = &sWT[d * WSTR + 4 * eg];
        u64 wA = *(const u64*)&wp[0];
        u64 wB = *(const u64*)&wp[2];
        float x0 = sX[rs * DD + d];
        float x1 = sX[(rs + 16) * DD + d];
        u64 x0p = pack2(x0, x0), x1p = pack2(x1, x1);
        acc0a = fma2(x0p, wA, acc0a);
        acc0b = fma2(x0p, wB, acc0b);
        acc1a = fma2(x1p, wA, acc1a);
        acc1b = fma2(x1p, wB, acc1b);
    }
    float o0, o1, o2, o3;
    unpack2(acc0a, o0, o1); unpack2(acc0b, o2, o3);
    *(float4*)&g_v[(row0 + rs) * DD + 4 * eg] = make_float4(o0, o1, o2, o3);
    unpack2(acc1a, o0, o1); unpack2(acc1b, o2, o3);
    *(float4*)&g_v[(row0 + rs + 16) * DD + 4 * eg] = make_float4(o0, o1, o2, o3);
}

// ---------------------------------------------------------------------------
// Kernel 2: pairwise RBF, f16x2 END-TO-END hot loop (no cvt in loop).
// Block = (b, upper-tri 64x64 tile pair), 256 threads, 4x4 elems/thread.
// Per 2-elem group per d: HADD2(diff) + LOP3(neg) + HMUL2(sq) +
// ex2.approx.f16x2 (ONE MUFU for 2 exps) + HADD2(den) + 2x HFMA2.
// f16 partials accumulate over 16-step chunks, promoted to f32 between
// chunks (bounds accumulation error at ~3e-4). Transposed [d][row] half
// smem, stride 66: all inner LDS.32 conflict-free or broadcast.
// ---------------------------------------------------------------------------
__global__ __launch_bounds__(256, 2)
void rbf_kernel(const float* __restrict__ x, float* __restrict__ out) {
    __shared__ __half XIh [DD * HSTR];   // +s*xi  [d*66 + row]
    __shared__ __half NXJh[DD * HSTR];   // -s*xj
    __shared__ __half VIh [DD * HSTR];
    __shared__ __half VJh [DD * HSTR];

    int b = blockIdx.y;
    int p = blockIdx.x;
    int ti = 0, rem = p;
    while (rem >= NT - ti) { rem -= NT - ti; ti++; }
    int tj = ti + rem;
    int i0 = ti * TILE, j0 = tj * TILE;

    int tid = threadIdx.x;
    const float* xb = x + b * TT * DD;
    const float* vb = g_v + b * TT * DD;

#pragma unroll
    for (int k = 0; k < 16; k++) {
        int idx = tid + k * 256;
        int r = idx >> 6, d = idx & 63;
        int sa = d * HSTR + r;
        XIh[sa]  = __float2half( SQRT_LOG2E * xb[i0 * DD + idx]);
        NXJh[sa] = __float2half(-SQRT_LOG2E * xb[j0 * DD + idx]);
        VIh[sa]  = __float2half(vb[i0 * DD + idx]);
        VJh[sa]  = __float2half(vb[j0 * DD + idx]);
    }
    __syncthreads();

    int tx = tid & 15, ty = tid >> 4;

    float2 denF[4][2], niF[4][2], njF[4][2];
#pragma unroll
    for (int r = 0; r < 4; r++)
#pragma unroll
        for (int c = 0; c < 2; c++) {
            denF[r][c] = make_float2(0.f, 0.f);
            niF[r][c]  = make_float2(0.f, 0.f);
            njF[r][c]  = make_float2(0.f, 0.f);
        }

#pragma unroll
    for (int chunk = 0; chunk < 4; chunk++) {
        h2 denH[4][2], niH[4][2], njH[4][2];
        h2 z = __float2half2_rn(0.f);
#pragma unroll
        for (int r = 0; r < 4; r++)
#pragma unroll
            for (int c = 0; c < 2; c++) { denH[r][c] = z; niH[r][c] = z; njH[r][c] = z; }

#pragma unroll
        for (int dd = 0; dd < 16; dd++) {
            int d = chunk * 16 + dd;
            const __half* Xd  = XIh  + d * HSTR;
            const __half* Vd  = VIh  + d * HSTR;
            const __half* NJd = NXJh + d * HSTR;
            const __half* JVd = VJh  + d * HSTR;

            // i rows: half2 fetches 2 rows at once (broadcast across tx)
            h2 fi01 = *(const h2*)&Xd[2 * ty];
            h2 fi23 = *(const h2*)&Xd[2 * ty + 32];
            h2 fv01 = *(const h2*)&Vd[2 * ty];
            h2 fv23 = *(const h2*)&Vd[2 * ty + 32];
            // j cols: half2 pairs, conflict-free across tx
            h2 njc[2], jvc[2];
            njc[0] = *(const h2*)&NJd[2 * tx];
            njc[1] = *(const h2*)&NJd[2 * tx + 32];
            jvc[0] = *(const h2*)&JVd[2 * tx];
            jvc[1] = *(const h2*)&JVd[2 * tx + 32];

            h2 fiD[4] = {__low2half2(fi01), __high2half2(fi01),
                         __low2half2(fi23), __high2half2(fi23)};
            h2 fvD[4] = {__low2half2(fv01), __high2half2(fv01),
                         __low2half2(fv23), __high2half2(fv23)};

#pragma unroll
            for (int r = 0; r < 4; r++) {
#pragma unroll
                for (int c = 0; c < 2; c++) {
                    h2 dif = __hadd2(fiD[r], njc[c]);      // s*(xi-xj)
                    h2 m   = h2neg(__hmul2(dif, dif));     // -t, LOP3+HMUL2
                    h2 e   = hex2(m);                      // ONE MUFU, 2 exps
                    denH[r][c] = __hadd2(denH[r][c], e);
                    niH[r][c]  = __hfma2(e, fvD[r], niH[r][c]);
                    njH[r][c]  = __hfma2(e, jvc[c], njH[r][c]);
                }
            }
        }

        // promote chunk partials to f32
#pragma unroll
        for (int r = 0; r < 4; r++)
#pragma unroll
            for (int c = 0; c < 2; c++) {
                float2 td = __half22float2(denH[r][c]);
                float2 tn = __half22float2(niH[r][c]);
                float2 tq = __half22float2(njH[r][c]);
                denF[r][c].x += td.x; denF[r][c].y += td.y;
                niF[r][c].x  += tn.x; niF[r][c].y  += tn.y;
                njF[r][c].x  += tq.x; njF[r][c].y  += tq.y;
            }
    }

    float* ob = out + (size_t)b * TT * TT;
    int rowOf[4] = {2 * ty, 2 * ty + 1, 2 * ty + 32, 2 * ty + 33};

    float oi[4][2][2], oj[4][2][2];
#pragma unroll
    for (int r = 0; r < 4; r++)
#pragma unroll
        for (int c = 0; c < 2; c++) {
            float rc0, rc1;
            asm("rcp.approx.ftz.f32 %0, %1;" : "=f"(rc0) : "f"(denF[r][c].x));
            asm("rcp.approx.ftz.f32 %0, %1;" : "=f"(rc1) : "f"(denF[r][c].y));
            oi[r][c][0] = niF[r][c].x * rc0; oi[r][c][1] = niF[r][c].y * rc1;
            oj[r][c][0] = njF[r][c].x * rc0; oj[r][c][1] = njF[r][c].y * rc1;
        }

    // main writes: float2, coalesced across tx
#pragma unroll
    for (int r = 0; r < 4; r++) {
        int gi = i0 + rowOf[r];
#pragma unroll
        for (int c = 0; c < 2; c++) {
            float2 w = make_float2(oi[r][c][0], oi[r][c][1]);
            *(float2*)&ob[(size_t)gi * TT + j0 + 2 * tx + 32 * c] = w;
        }
    }

    if (ti != tj) {
        // mirror: out[b, gj, gi..gi+1]
#pragma unroll
        for (int c = 0; c < 2; c++) {
#pragma unroll
            for (int e = 0; e < 2; e++) {
                int gj = j0 + 2 * tx + 32 * c + e;
                float2 w0 = make_float2(oj[0][c][e], oj[1][c][e]);
                float2 w1 = make_float2(oj[2][c][e], oj[3][c][e]);
                *(float2*)&ob[(size_t)gj * TT + i0 + 2 * ty]      = w0;
                *(float2*)&ob[(size_t)gj * TT + i0 + 2 * ty + 32] = w1;
            }
        }
    }
}

extern "C" void kernel_launch(void* const* d_in, const int* in_sizes, int n_in,
                              void* d_out, int out_size) {
    const float* x = (const float*)d_in[0];    // (8,512,64)
    const float* W = (const float*)d_in[1];    // (64,64)
    const float* bias = (const float*)d_in[2]; // (64,)
    float* out = (float*)d_out;                // (8,512,512)

    v_kernel<<<(BB * TT) / 32, 256>>>(x, W, bias);
    rbf_kernel<<<dim3(NPAIR, BB), 256>>>(x, out);
}

// round 10
// speedup vs baseline: 1.1404x; 1.0066x over previous
#include <cuda_runtime.h>
#include <cuda_fp16.h>

#define BB 8
#define TT 512
#define DD 64
#define TILE 32
#define NT (TT / TILE)               // 16 tiles per dim
#define NPAIR (NT * (NT + 1) / 2)    // 136 upper-tri tile pairs
#define HSTR 34                       // transposed [d][row] stride (halves)

// sqrt(log2(e)): pre-scale x so exp(-(dx)^2) = ex2(-(s*dx)^2)
#define SQRT_LOG2E 1.2011224087864498f

typedef unsigned long long u64;
typedef __half2 h2;

__device__ float g_v[BB * TT * DD];   // scratch: v = x @ W^T + b (512 KB)

// ---- f32x2 packed helpers ---------------------------------------------------
__device__ __forceinline__ u64 pack2(float lo, float hi) {
    u64 r; asm("mov.b64 %0, {%1, %2};" : "=l"(r) : "f"(lo), "f"(hi)); return r;
}
__device__ __forceinline__ void unpack2(u64 v, float& lo, float& hi) {
    asm("mov.b64 {%0, %1}, %2;" : "=f"(lo), "=f"(hi) : "l"(v));
}
__device__ __forceinline__ u64 add2(u64 a, u64 b) {
    u64 r; asm("add.rn.f32x2 %0, %1, %2;" : "=l"(r) : "l"(a), "l"(b)); return r;
}
__device__ __forceinline__ u64 fma2(u64 a, u64 b, u64 c) {
    u64 r; asm("fma.rn.f32x2 %0, %1, %2, %3;" : "=l"(r) : "l"(a), "l"(b), "l"(c)); return r;
}

// ---- f16x2 helpers ---------------------------------------------------------
__device__ __forceinline__ h2 h2neg(h2 a) {
    unsigned u = *(unsigned*)&a;
    u ^= 0x80008000u;
    return *(h2*)&u;
}
__device__ __forceinline__ h2 hex2(h2 a) {
    unsigned r, u = *(unsigned*)&a;
    asm("ex2.approx.f16x2 %0, %1;" : "=r"(r) : "r"(u));
    return *(h2*)&r;
}

// ---------------------------------------------------------------------------
// Kernel 1: v[b,t,e] = sum_d x[b,t,d] * W[e,d] + bias[e]
// 128 blocks x 256 threads, 32 rows/block; f32x2 FMAs. (unchanged, works)
// ---------------------------------------------------------------------------
#define WSTR 68
__global__ __launch_bounds__(256)
void v_kernel(const float* __restrict__ x, const float* __restrict__ W,
              const float* __restrict__ bias) {
    __shared__ float sWT[DD * WSTR];     // sWT[d*68 + e] = W[e*64 + d]
    __shared__ float sX[32 * DD];

    int tid = threadIdx.x;
    int row0 = blockIdx.x * 32;

    for (int k = tid; k < DD * DD; k += 256) {
        int e = k >> 6, d = k & 63;
        sWT[d * WSTR + e] = W[k];
    }
    for (int k = tid; k < 32 * DD; k += 256)
        sX[k] = x[row0 * DD + k];
    __syncthreads();

    int eg = tid & 15;
    int rs = tid >> 4;
    float4 b4 = *(const float4*)&bias[4 * eg];
    u64 acc0a = pack2(b4.x, b4.y), acc0b = pack2(b4.z, b4.w);
    u64 acc1a = acc0a, acc1b = acc0b;

#pragma unroll 8
    for (int d = 0; d < DD; d++) {
        const float* wp = &sWT[d * WSTR + 4 * eg];
        u64 wA = *(const u64*)&wp[0];
        u64 wB = *(const u64*)&wp[2];
        float x0 = sX[rs * DD + d];
        float x1 = sX[(rs + 16) * DD + d];
        u64 x0p = pack2(x0, x0), x1p = pack2(x1, x1);
        acc0a = fma2(x0p, wA, acc0a);
        acc0b = fma2(x0p, wB, acc0b);
        acc1a = fma2(x1p, wA, acc1a);
        acc1b = fma2(x1p, wB, acc1b);
    }
    float o0, o1, o2, o3;
    unpack2(acc0a, o0, o1); unpack2(acc0b, o2, o3);
    *(float4*)&g_v[(row0 + rs) * DD + 4 * eg] = make_float4(o0, o1, o2, o3);
    unpack2(acc1a, o0, o1); unpack2(acc1b, o2, o3);
    *(float4*)&g_v[(row0 + rs + 16) * DD + 4 * eg] = make_float4(o0, o1, o2, o3);
}

// ---------------------------------------------------------------------------
// Kernel 2: pairwise RBF, f16x2 hot loop on a HIGH-OCCUPANCY small-tile
// geometry. Block = (b, upper-tri 32x32 tile pair) -> 1088 streaming blocks,
// 17.4KB smem, <=64 regs -> 4 CTAs/SM, 32 warps/SM. Thread (tx,ty) owns
// rows {2ty,2ty+1} x j-cols {2tx,2tx+1} = 2 h2 groups. Per group per d:
// HADD2 + HMUL2 + LOP3 + ex2.f16x2 (1 MUFU, 2 exps) + HADD2 + 2x HFMA2.
// f16 partials over 16-d chunks, promoted to f32x2 (identical numerics to
// the passing R9 kernel). Transposed [d][row] smem: conflict-free LDS.
// ---------------------------------------------------------------------------
__global__ __launch_bounds__(256, 4)
void rbf_kernel(const float* __restrict__ x, float* __restrict__ out) {
    __shared__ __half XIh [DD * HSTR];   // +s*xi  [d*34 + row]
    __shared__ __half NXJh[DD * HSTR];   // -s*xj
    __shared__ __half VIh [DD * HSTR];
    __shared__ __half VJh [DD * HSTR];

    int b = blockIdx.y;
    int p = blockIdx.x;
    int ti = 0, rem = p;
    while (rem >= NT - ti) { rem -= NT - ti; ti++; }
    int tj = ti + rem;
    int i0 = ti * TILE, j0 = tj * TILE;

    int tid = threadIdx.x;
    const float* xb = x + b * TT * DD;
    const float* vb = g_v + b * TT * DD;

    // Stage 32 rows x 64 d per array, transposed. Coalesced LDG; STS.16
    // across consecutive d -> 17-word stride -> all 32 banks distinct.
#pragma unroll
    for (int k = 0; k < 8; k++) {
        int idx = tid + k * 256;             // [0, 2048)
        int r = idx >> 6, d = idx & 63;
        int sa = d * HSTR + r;
        XIh[sa]  = __float2half( SQRT_LOG2E * xb[i0 * DD + idx]);
        NXJh[sa] = __float2half(-SQRT_LOG2E * xb[j0 * DD + idx]);
        VIh[sa]  = __float2half(vb[i0 * DD + idx]);
        VJh[sa]  = __float2half(vb[j0 * DD + idx]);
    }
    __syncthreads();

    int tx = tid & 15, ty = tid >> 4;        // 16x16 thread grid

    u64 denF[2], niF[2], njF[2];             // f32x2 accumulators
#pragma unroll
    for (int r = 0; r < 2; r++) { denF[r] = 0ULL; niF[r] = 0ULL; njF[r] = 0ULL; }

    for (int chunk = 0; chunk < 4; chunk++) {
        h2 denH[2], niH[2], njH[2];
        h2 z = __float2half2_rn(0.f);
#pragma unroll
        for (int r = 0; r < 2; r++) { denH[r] = z; niH[r] = z; njH[r] = z; }

#pragma unroll
        for (int dd = 0; dd < 16; dd++) {
            int d = chunk * 16 + dd;
            const __half* Xd  = XIh  + d * HSTR;
            const __half* Vd  = VIh  + d * HSTR;
            const __half* NJd = NXJh + d * HSTR;
            const __half* JVd = VJh  + d * HSTR;

            h2 fiP = *(const h2*)&Xd[2 * ty];     // rows 2ty,2ty+1 (bcast)
            h2 fvP = *(const h2*)&Vd[2 * ty];
            h2 njc = *(const h2*)&NJd[2 * tx];    // cols 2tx,2tx+1 (spread)
            h2 jvc = *(const h2*)&JVd[2 * tx];

            h2 fiD[2] = {__low2half2(fiP), __high2half2(fiP)};  // -> selectors
            h2 fvD[2] = {__low2half2(fvP), __high2half2(fvP)};

#pragma unroll
            for (int r = 0; r < 2; r++) {
                h2 dif = __hadd2(fiD[r], njc);     // s*(xi-xj)
                h2 m   = h2neg(__hmul2(dif, dif)); // -t
                h2 e   = hex2(m);                  // ONE MUFU, 2 exps
                denH[r] = __hadd2(denH[r], e);
                niH[r]  = __hfma2(e, fvD[r], niH[r]);
                njH[r]  = __hfma2(e, jvc, njH[r]);
            }
        }

        // promote chunk partials to f32x2
#pragma unroll
        for (int r = 0; r < 2; r++) {
            float2 td = __half22float2(denH[r]);
            float2 tn = __half22float2(niH[r]);
            float2 tq = __half22float2(njH[r]);
            denF[r] = add2(denF[r], pack2(td.x, td.y));
            niF[r]  = add2(niF[r],  pack2(tn.x, tn.y));
            njF[r]  = add2(njF[r],  pack2(tq.x, tq.y));
        }
    }

    float* ob = out + (size_t)b * TT * TT;

    float oi[2][2], oj[2][2];
#pragma unroll
    for (int r = 0; r < 2; r++) {
        float d0, d1, n0, n1, q0, q1;
        unpack2(denF[r], d0, d1);
        unpack2(niF[r],  n0, n1);
        unpack2(njF[r],  q0, q1);
        float rc0, rc1;
        asm("rcp.approx.ftz.f32 %0, %1;" : "=f"(rc0) : "f"(d0));
        asm("rcp.approx.ftz.f32 %0, %1;" : "=f"(rc1) : "f"(d1));
        oi[r][0] = n0 * rc0; oi[r][1] = n1 * rc1;
        oj[r][0] = q0 * rc0; oj[r][1] = q1 * rc1;
    }

    // main writes: out[b, i0+2ty+r, j0+2tx .. +1] — float2, coalesced in tx
#pragma unroll
    for (int r = 0; r < 2; r++) {
        int gi = i0 + 2 * ty + r;
        float2 w = make_float2(oi[r][0], oi[r][1]);
        *(float2*)&ob[(size_t)gi * TT + j0 + 2 * tx] = w;
    }

    if (ti != tj) {
        // mirror: out[b, j0+2tx+e, i0+2ty .. +1]
#pragma unroll
        for (int e = 0; e < 2; e++) {
            int gj = j0 + 2 * tx + e;
            float2 w = make_float2(oj[0][e], oj[1][e]);
            *(float2*)&ob[(size_t)gj * TT + i0 + 2 * ty] = w;
        }
    }
}

extern "C" void kernel_launch(void* const* d_in, const int* in_sizes, int n_in,
                              void* d_out, int out_size) {
    const float* x = (const float*)d_in[0];    // (8,512,64)
    const float* W = (const float*)d_in[1];    // (64,64)
    const float* bias = (const float*)d_in[2]; // (64,)
    float* out = (float*)d_out;                // (8,512,512)

    v_kernel<<<(BB * TT) / 32, 256>>>(x, W, bias);
    rbf_kernel<<<dim3(NPAIR, BB), 256>>>(x, out);
}

// round 11
// speedup vs baseline: 1.2150x; 1.0654x over previous
#include <cuda_runtime.h>
#include <cuda_fp16.h>

#define BB 8
#define TT 512
#define DD 64
#define TILE 32
#define NT (TT / TILE)               // 16 tiles per dim
#define NPAIR (NT * (NT + 1) / 2)    // 136 upper-tri tile pairs

// sqrt(log2(e)): pre-scale x so exp(-(dx)^2) = ex2(-(s*dx)^2)
#define SQRT_LOG2E 1.2011224087864498f

typedef unsigned long long u64;
typedef __half2 h2;

// Precomputed half-precision operands (written by v_kernel):
__device__ __half g_xh[BB * TT * DD];   // s * x   (256 KB)
__device__ __half g_vh[BB * TT * DD];   // v = xW^T + b (256 KB)

// ---- f32x2 packed helpers (v_kernel GEMM) ---------------------------------
__device__ __forceinline__ u64 pack2(float lo, float hi) {
    u64 r; asm("mov.b64 %0, {%1, %2};" : "=l"(r) : "f"(lo), "f"(hi)); return r;
}
__device__ __forceinline__ void unpack2(u64 v, float& lo, float& hi) {
    asm("mov.b64 {%0, %1}, %2;" : "=f"(lo), "=f"(hi) : "l"(v));
}
__device__ __forceinline__ u64 fma2(u64 a, u64 b, u64 c) {
    u64 r; asm("fma.rn.f32x2 %0, %1, %2, %3;" : "=l"(r) : "l"(a), "l"(b), "l"(c)); return r;
}

// ---- f16x2 helpers ---------------------------------------------------------
__device__ __forceinline__ h2 u2h(unsigned u) { return *(h2*)&u; }
// returns exp2(-m) elementwise for m >= 0: LOP3 (sign flip) + ONE MUFU.EX2
__device__ __forceinline__ h2 ex2neg(h2 m) {
    unsigned u = *(unsigned*)&m ^ 0x80008000u;
    unsigned r; asm("ex2.approx.f16x2 %0, %1;" : "=r"(r) : "r"(u));
    return *(h2*)&r;
}

// ---------------------------------------------------------------------------
// Kernel 1: v = x @ W^T + b, plus half-precision operand preparation:
// writes g_xh = half(s*x) and g_vh = half(v). 128 blocks x 256 threads.
// ---------------------------------------------------------------------------
#define WSTR 68
__global__ __launch_bounds__(256)
void v_kernel(const float* __restrict__ x, const float* __restrict__ W,
              const float* __restrict__ bias) {
    __shared__ float sWT[DD * WSTR];     // sWT[d*68 + e] = W[e*64 + d]
    __shared__ float sX[32 * DD];

    int tid = threadIdx.x;
    int row0 = blockIdx.x * 32;

    for (int k = tid; k < DD * DD; k += 256) {
        int e = k >> 6, d = k & 63;
        sWT[d * WSTR + e] = W[k];
    }
    for (int k = tid; k < 32 * DD; k += 256)
        sX[k] = x[row0 * DD + k];
    __syncthreads();

    // Emit g_xh = half(s*x) for these 32 rows (1024 u32 / block)
#pragma unroll
    for (int k = 0; k < 4; k++) {
        int lin = tid + 256 * k;             // [0, 1024)
        int r = lin >> 5, q = lin & 31;      // row, u32-within-row
        float a0 = sX[r * DD + 2 * q];
        float a1 = sX[r * DD + 2 * q + 1];
        h2 hv = __floats2half2_rn(SQRT_LOG2E * a0, SQRT_LOG2E * a1);
        ((unsigned*)g_xh)[(row0 + r) * 32 + q] = *(unsigned*)&hv;
    }

    int eg = tid & 15;                   // e = 4*eg .. 4*eg+3
    int rs = tid >> 4;                   // rows rs, rs+16
    float4 b4 = *(const float4*)&bias[4 * eg];
    u64 acc0a = pack2(b4.x, b4.y), acc0b = pack2(b4.z, b4.w);
    u64 acc1a = acc0a, acc1b = acc0b;

#pragma unroll 8
    for (int d = 0; d < DD; d++) {
        const float* wp = &sWT[d * WSTR + 4 * eg];
        u64 wA = *(const u64*)&wp[0];
        u64 wB = *(const u64*)&wp[2];
        float x0 = sX[rs * DD + d];
        float x1 = sX[(rs + 16) * DD + d];
        u64 x0p = pack2(x0, x0), x1p = pack2(x1, x1);
        acc0a = fma2(x0p, wA, acc0a);
        acc0b = fma2(x0p, wB, acc0b);
        acc1a = fma2(x1p, wA, acc1a);
        acc1b = fma2(x1p, wB, acc1b);
    }
    float o0, o1, o2, o3;
    uint2 st;
    unpack2(acc0a, o0, o1); unpack2(acc0b, o2, o3);
    { h2 pA = __floats2half2_rn(o0, o1), pB = __floats2half2_rn(o2, o3);
      st.x = *(unsigned*)&pA; st.y = *(unsigned*)&pB; }
    *(uint2*)&g_vh[(row0 + rs) * DD + 4 * eg] = st;
    unpack2(acc1a, o0, o1); unpack2(acc1b, o2, o3);
    { h2 pA = __floats2half2_rn(o0, o1), pB = __floats2half2_rn(o2, o3);
      st.x = *(unsigned*)&pA; st.y = *(unsigned*)&pB; }
    *(uint2*)&g_vh[(row0 + rs + 16) * DD + 4 * eg] = st;
}

// ---------------------------------------------------------------------------
// Kernel 2: pairwise RBF. d-PACKED f16x2 hot loop: each h2 carries two d's
// of ONE (i,j) pair; den/ni/nj accumulate per-pair in h2 (lo/hi folded at
// the end). Thread (tx,ty) owns rows {2ty,2ty+1} x cols {tx, tx+16} -> 8
// independent exp chains per 4-d step. Layout [row][d] (64 halves/row):
// i-arrays linear (phase-broadcast: lanes 0-15 share ty), j-arrays XOR-
// swizzled in 8B units (u' = u ^ (col&15)) so LDS.64 across tx is
// conflict-free. Staging = pure u32 copies from g_xh/g_vh (+1 XOR for -s*xj).
// ---------------------------------------------------------------------------
#define OFF_VI  2048     // half offsets within shared
#define OFF_NXJ 4096
#define OFF_VJ  6144

__global__ __launch_bounds__(256, 4)
void rbf_kernel(float* __restrict__ out) {
    __shared__ __align__(16) __half Sh[8192];   // 16 KB: XI | VI | NXJ | VJ

    int b = blockIdx.y;
    int p = blockIdx.x;
    int ti = 0, rem = p;
    while (rem >= NT - ti) { rem -= NT - ti; ti++; }
    int tj = ti + rem;
    int i0 = ti * TILE, j0 = tj * TILE;

    int tid = threadIdx.x;
    const unsigned* gx = (const unsigned*)g_xh;
    const unsigned* gv = (const unsigned*)g_vh;
    unsigned* S32 = (unsigned*)Sh;
    int baseI = (b * TT + i0) * 32;
    int baseJ = (b * TT + j0) * 32;

#pragma unroll
    for (int k = 0; k < 4; k++) {
        int lin = tid + 256 * k;             // [0, 1024) = r*32 + q
        int r = lin >> 5, q = lin & 31;
        int u = q >> 1, lo = q & 1;
        int sw = r * 32 + (((u ^ (r & 15)) << 1) | lo);   // swizzled u32 slot
        S32[lin]                 = gx[baseI + lin];                 // XI
        S32[(OFF_VI >> 1) + lin] = gv[baseI + lin];                 // VI
        S32[(OFF_NXJ >> 1) + sw] = gx[baseJ + lin] ^ 0x80008000u;   // -s*xj
        S32[(OFF_VJ >> 1) + sw]  = gv[baseJ + lin];                 // VJ
    }
    __syncthreads();

    int tx = tid & 15, ty = tid >> 4;
    const __half* pi = Sh + 2 * ty * 64;             // XI row 2ty (VI at +OFF_VI)
    const __half* pj = Sh + OFF_NXJ + tx * 64;       // NXJ col tx (VJ at +2048)

    float denF[2][2], niF[2][2], njF[2][2];
#pragma unroll
    for (int r = 0; r < 2; r++)
#pragma unroll
        for (int c = 0; c < 2; c++) { denF[r][c] = 0.f; niF[r][c] = 0.f; njF[r][c] = 0.f; }

#pragma unroll
    for (int ch = 0; ch < 2; ch++) {         // 2 chunks of 32 d
        h2 dH[2][2], nH[2][2], qH[2][2];
        h2 z = __float2half2_rn(0.f);
#pragma unroll
        for (int r = 0; r < 2; r++)
#pragma unroll
            for (int c = 0; c < 2; c++) { dH[r][c] = z; nH[r][c] = z; qH[r][c] = z; }

#pragma unroll
        for (int s = 0; s < 8; s++) {        // 4 d's per step
            int u = ch * 8 + s;
            int uj = u ^ tx;                  // swizzled 8B slot for j-arrays

            uint2 fiA = *(const uint2*)(pi + 4 * u);                 // row 2ty
            uint2 fiB = *(const uint2*)(pi + 64 + 4 * u);            // row 2ty+1
            uint2 fvA = *(const uint2*)(pi + OFF_VI + 4 * u);
            uint2 fvB = *(const uint2*)(pi + OFF_VI + 64 + 4 * u);
            uint2 njA = *(const uint2*)(pj + 4 * uj);                // col tx
            uint2 njB = *(const uint2*)(pj + 1024 + 4 * uj);         // col tx+16
            uint2 jvA = *(const uint2*)(pj + 2048 + 4 * uj);
            uint2 jvB = *(const uint2*)(pj + 2048 + 1024 + 4 * uj);

            h2 fi[2][2] = {{u2h(fiA.x), u2h(fiA.y)}, {u2h(fiB.x), u2h(fiB.y)}};
            h2 fv[2][2] = {{u2h(fvA.x), u2h(fvA.y)}, {u2h(fvB.x), u2h(fvB.y)}};
            h2 nj[2][2] = {{u2h(njA.x), u2h(njA.y)}, {u2h(njB.x), u2h(njB.y)}};
            h2 jv[2][2] = {{u2h(jvA.x), u2h(jvA.y)}, {u2h(jvB.x), u2h(jvB.y)}};

#pragma unroll
            for (int r = 0; r < 2; r++)
#pragma unroll
                for (int c = 0; c < 2; c++)
#pragma unroll
                    for (int s2 = 0; s2 < 2; s2++) {
                        h2 dif = __hadd2(fi[r][s2], nj[c][s2]);   // s*(xi-xj), 2 d's
                        h2 m   = __hmul2(dif, dif);
                        h2 e   = ex2neg(m);                       // LOP3 + 1 MUFU
                        dH[r][c] = __hadd2(dH[r][c], e);
                        nH[r][c] = __hfma2(e, fv[r][s2], nH[r][c]);
                        qH[r][c] = __hfma2(e, jv[c][s2], qH[r][c]);
                    }
        }

        // fold chunk partials (lo+hi are different d's of the same pair)
#pragma unroll
        for (int r = 0; r < 2; r++)
#pragma unroll
            for (int c = 0; c < 2; c++) {
                float2 t;
                t = __half22float2(dH[r][c]); denF[r][c] += t.x + t.y;
                t = __half22float2(nH[r][c]); niF[r][c]  += t.x + t.y;
                t = __half22float2(qH[r][c]); njF[r][c]  += t.x + t.y;
            }
    }

    float* ob = out + (size_t)b * TT * TT;

#pragma unroll
    for (int r = 0; r < 2; r++) {
        int gi = i0 + 2 * ty + r;
#pragma unroll
        for (int c = 0; c < 2; c++) {
            int gj = j0 + tx + 16 * c;
            float rc;
            asm("rcp.approx.ftz.f32 %0, %1;" : "=f"(rc) : "f"(denF[r][c]));
            ob[(size_t)gi * TT + gj] = niF[r][c] * rc;   // coalesced across tx
            if (ti != tj)
                ob[(size_t)gj * TT + gi] = njF[r][c] * rc;   // mirror
        }
    }
}

extern "C" void kernel_launch(void* const* d_in, const int* in_sizes, int n_in,
                              void* d_out, int out_size) {
    const float* x = (const float*)d_in[0];    // (8,512,64)
    const float* W = (const float*)d_in[1];    // (64,64)
    const float* bias = (const float*)d_in[2]; // (64,)
    float* out = (float*)d_out;                // (8,512,512)

    v_kernel<<<(BB * TT) / 32, 256>>>(x, W, bias);
    rbf_kernel<<<dim3(NPAIR, BB), 256>>>(out);
}

// round 12
// speedup vs baseline: 1.2279x; 1.0106x over previous
#include <cuda_runtime.h>
#include <cuda_fp16.h>

#define BB 8
#define TT 512
#define DD 64
#define TILE 32
#define NT (TT / TILE)               // 16 tiles per dim
#define NPAIR (NT * (NT + 1) / 2)    // 136 upper-tri tile pairs

// sqrt(log2(e)): pre-scale x so exp(-(dx)^2) = ex2(-(s*dx)^2)
#define SQRT_LOG2E 1.2011224087864498f
#define SGN2 0x80008000u

typedef unsigned long long u64;
typedef __half2 h2;

// Precomputed half-precision operands (written by v_kernel):
__device__ __half g_xh[BB * TT * DD];   // s * x   (256 KB)
__device__ __half g_vh[BB * TT * DD];   // v = xW^T + b (256 KB)

// ---- f32x2 packed helpers (v_kernel GEMM) ---------------------------------
__device__ __forceinline__ u64 pack2(float lo, float hi) {
    u64 r; asm("mov.b64 %0, {%1, %2};" : "=l"(r) : "f"(lo), "f"(hi)); return r;
}
__device__ __forceinline__ void unpack2(u64 v, float& lo, float& hi) {
    asm("mov.b64 {%0, %1}, %2;" : "=f"(lo), "=f"(hi) : "l"(v));
}
__device__ __forceinline__ u64 fma2(u64 a, u64 b, u64 c) {
    u64 r; asm("fma.rn.f32x2 %0, %1, %2, %3;" : "=l"(r) : "l"(a), "l"(b), "l"(c)); return r;
}

// ---- f16x2 helpers ---------------------------------------------------------
__device__ __forceinline__ h2 u2h(unsigned u) { return *(h2*)&u; }
// e = exp2(-(dif^2)): HMUL2 with folded source negation + ONE MUFU.EX2.
// (-dif)*dif == -(dif*dif) exactly in IEEE; ptxas folds HNEG2 into HMUL2.
__device__ __forceinline__ h2 ex2negsq(h2 dif) {
    h2 m = __hmul2(__hneg2(dif), dif);
    unsigned r, u = *(unsigned*)&m;
    asm("ex2.approx.f16x2 %0, %1;" : "=r"(r) : "r"(u));
    return *(h2*)&r;
}

// ---------------------------------------------------------------------------
// Kernel 1: v = x @ W^T + b, plus half operand prep: g_xh = half(s*x),
// g_vh = half(v). 128 blocks x 256 threads.
// ---------------------------------------------------------------------------
#define WSTR 68
__global__ __launch_bounds__(256)
void v_kernel(const float* __restrict__ x, const float* __restrict__ W,
              const float* __restrict__ bias) {
    __shared__ float sWT[DD * WSTR];     // sWT[d*68 + e] = W[e*64 + d]
    __shared__ float sX[32 * DD];

    int tid = threadIdx.x;
    int row0 = blockIdx.x * 32;

    for (int k = tid; k < DD * DD; k += 256) {
        int e = k >> 6, d = k & 63;
        sWT[d * WSTR + e] = W[k];
    }
    for (int k = tid; k < 32 * DD; k += 256)
        sX[k] = x[row0 * DD + k];
    __syncthreads();

    // Emit g_xh = half(s*x) for these 32 rows (1024 u32 / block)
#pragma unroll
    for (int k = 0; k < 4; k++) {
        int lin = tid + 256 * k;             // [0, 1024)
        int r = lin >> 5, q = lin & 31;
        float a0 = sX[r * DD + 2 * q];
        float a1 = sX[r * DD + 2 * q + 1];
        h2 hv = __floats2half2_rn(SQRT_LOG2E * a0, SQRT_LOG2E * a1);
        ((unsigned*)g_xh)[(row0 + r) * 32 + q] = *(unsigned*)&hv;
    }

    int eg = tid & 15;                   // e = 4*eg .. 4*eg+3
    int rs = tid >> 4;                   // rows rs, rs+16
    float4 b4 = *(const float4*)&bias[4 * eg];
    u64 acc0a = pack2(b4.x, b4.y), acc0b = pack2(b4.z, b4.w);
    u64 acc1a = acc0a, acc1b = acc0b;

#pragma unroll 8
    for (int d = 0; d < DD; d++) {
        const float* wp = &sWT[d * WSTR + 4 * eg];
        u64 wA = *(const u64*)&wp[0];
        u64 wB = *(const u64*)&wp[2];
        float x0 = sX[rs * DD + d];
        float x1 = sX[(rs + 16) * DD + d];
        u64 x0p = pack2(x0, x0), x1p = pack2(x1, x1);
        acc0a = fma2(x0p, wA, acc0a);
        acc0b = fma2(x0p, wB, acc0b);
        acc1a = fma2(x1p, wA, acc1a);
        acc1b = fma2(x1p, wB, acc1b);
    }
    float o0, o1, o2, o3;
    uint2 st;
    unpack2(acc0a, o0, o1); unpack2(acc0b, o2, o3);
    { h2 pA = __floats2half2_rn(o0, o1), pB = __floats2half2_rn(o2, o3);
      st.x = *(unsigned*)&pA; st.y = *(unsigned*)&pB; }
    *(uint2*)&g_vh[(row0 + rs) * DD + 4 * eg] = st;
    unpack2(acc1a, o0, o1); unpack2(acc1b, o2, o3);
    { h2 pA = __floats2half2_rn(o0, o1), pB = __floats2half2_rn(o2, o3);
      st.x = *(unsigned*)&pA; st.y = *(unsigned*)&pB; }
    *(uint2*)&g_vh[(row0 + rs + 16) * DD + 4 * eg] = st;
}

// ---------------------------------------------------------------------------
// Kernel 2: pairwise RBF. d-PACKED f16x2 hot loop: each h2 = two d's of ONE
// (i,j) pair. Per group: HADD2 + HMUL2(src-neg) + MUFU + HADD2 + 2x HFMA2
// (6 issue slots, no ALU op). Thread (tx,ty): rows {2ty,2ty+1} x cols
// {tx, tx+16} -> 8 independent exp chains per 4-d step. Layout [row][d];
// j-arrays XOR-swizzled in 8B units (u' = u ^ col15) -> conflict-free LDS.64.
// Staging: 4x LDG.128 per thread from precomputed g_xh/g_vh.
// ---------------------------------------------------------------------------
#define OFF_VI  2048     // half offsets within shared
#define OFF_NXJ 4096
#define OFF_VJ  6144

__global__ __launch_bounds__(256, 4)
void rbf_kernel(float* __restrict__ out) {
    __shared__ __align__(16) __half Sh[8192];   // 16 KB: XI | VI | NXJ | VJ

    int b = blockIdx.y;
    int p = blockIdx.x;
    int ti = 0, rem = p;
    while (rem >= NT - ti) { rem -= NT - ti; ti++; }
    int tj = ti + rem;
    int i0 = ti * TILE, j0 = tj * TILE;

    int tid = threadIdx.x;
    const unsigned* gx = (const unsigned*)g_xh;
    const unsigned* gv = (const unsigned*)g_vh;
    unsigned* S32 = (unsigned*)Sh;
    int baseI = (b * TT + i0) * 32;
    int baseJ = (b * TT + j0) * 32;

    // Stage: each thread owns u32s [4*tid, 4*tid+4) = row r, quads q0..q0+3.
    {
        int r = tid >> 3, q0 = (tid & 7) * 4;
        int lin = r * 32 + q0;
        uint4 xi4 = *(const uint4*)&gx[baseI + lin];
        uint4 vi4 = *(const uint4*)&gv[baseI + lin];
        uint4 xj4 = *(const uint4*)&gx[baseJ + lin];
        uint4 vj4 = *(const uint4*)&gv[baseJ + lin];

        *(uint4*)&S32[lin] = xi4;                         // XI linear
        *(uint4*)&S32[(OFF_VI >> 1) + lin] = vi4;         // VI linear

        int msk = r & 15;
        int u0 = (q0 >> 1) ^ msk;        // swizzled 8B slot for (q0,q0+1)
        int u1 = u0 ^ 1;                 // slot for (q0+2,q0+3)
        *(uint2*)&S32[(OFF_NXJ >> 1) + r * 32 + 2 * u0] =
            make_uint2(xj4.x ^ SGN2, xj4.y ^ SGN2);       // -s*xj
        *(uint2*)&S32[(OFF_NXJ >> 1) + r * 32 + 2 * u1] =
            make_uint2(xj4.z ^ SGN2, xj4.w ^ SGN2);
        *(uint2*)&S32[(OFF_VJ >> 1) + r * 32 + 2 * u0] = make_uint2(vj4.x, vj4.y);
        *(uint2*)&S32[(OFF_VJ >> 1) + r * 32 + 2 * u1] = make_uint2(vj4.z, vj4.w);
    }
    __syncthreads();

    int tx = tid & 15, ty = tid >> 4;
    const __half* pi = Sh + 2 * ty * 64;             // XI row 2ty (VI at +OFF_VI)
    const __half* pj = Sh + OFF_NXJ + tx * 64;       // NXJ col tx (VJ at +2048)

    float denF[2][2], niF[2][2], njF[2][2];
#pragma unroll
    for (int r = 0; r < 2; r++)
#pragma unroll
        for (int c = 0; c < 2; c++) { denF[r][c] = 0.f; niF[r][c] = 0.f; njF[r][c] = 0.f; }

#pragma unroll
    for (int ch = 0; ch < 2; ch++) {         // 2 chunks of 32 d
        h2 dH[2][2], nH[2][2], qH[2][2];
        h2 z = __float2half2_rn(0.f);
#pragma unroll
        for (int r = 0; r < 2; r++)
#pragma unroll
            for (int c = 0; c < 2; c++) { dH[r][c] = z; nH[r][c] = z; qH[r][c] = z; }

#pragma unroll
        for (int s = 0; s < 8; s++) {        // 4 d's per step
            int u = ch * 8 + s;
            int uj = u ^ tx;                  // swizzled 8B slot for j-arrays

            uint2 fiA = *(const uint2*)(pi + 4 * u);                 // row 2ty
            uint2 fiB = *(const uint2*)(pi + 64 + 4 * u);            // row 2ty+1
            uint2 fvA = *(const uint2*)(pi + OFF_VI + 4 * u);
            uint2 fvB = *(const uint2*)(pi + OFF_VI + 64 + 4 * u);
            uint2 njA = *(const uint2*)(pj + 4 * uj);                // col tx
            uint2 njB = *(const uint2*)(pj + 1024 + 4 * uj);         // col tx+16
            uint2 jvA = *(const uint2*)(pj + 2048 + 4 * uj);
            uint2 jvB = *(const uint2*)(pj + 2048 + 1024 + 4 * uj);

            h2 fi[2][2] = {{u2h(fiA.x), u2h(fiA.y)}, {u2h(fiB.x), u2h(fiB.y)}};
            h2 fv[2][2] = {{u2h(fvA.x), u2h(fvA.y)}, {u2h(fvB.x), u2h(fvB.y)}};
            h2 nj[2][2] = {{u2h(njA.x), u2h(njA.y)}, {u2h(njB.x), u2h(njB.y)}};
            h2 jv[2][2] = {{u2h(jvA.x), u2h(jvA.y)}, {u2h(jvB.x), u2h(jvB.y)}};

#pragma unroll
            for (int r = 0; r < 2; r++)
#pragma unroll
                for (int c = 0; c < 2; c++)
#pragma unroll
                    for (int s2 = 0; s2 < 2; s2++) {
                        h2 dif = __hadd2(fi[r][s2], nj[c][s2]);   // s*(xi-xj)
                        h2 e   = ex2negsq(dif);                   // HMUL2(neg)+MUFU
                        dH[r][c] = __hadd2(dH[r][c], e);
                        nH[r][c] = __hfma2(e, fv[r][s2], nH[r][c]);
                        qH[r][c] = __hfma2(e, jv[c][s2], qH[r][c]);
                    }
        }

        // fold chunk partials (lo+hi are different d's of the same pair)
#pragma unroll
        for (int r = 0; r < 2; r++)
#pragma unroll
            for (int c = 0; c < 2; c++) {
                float2 t;
                t = __half22float2(dH[r][c]); denF[r][c] += t.x + t.y;
                t = __half22float2(nH[r][c]); niF[r][c]  += t.x + t.y;
                t = __half22float2(qH[r][c]); njF[r][c]  += t.x + t.y;
            }
    }

    float* ob = out + (size_t)b * TT * TT;

#pragma unroll
    for (int r = 0; r < 2; r++) {
        int gi = i0 + 2 * ty + r;
#pragma unroll
        for (int c = 0; c < 2; c++) {
            int gj = j0 + tx + 16 * c;
            float rc;
            asm("rcp.approx.ftz.f32 %0, %1;" : "=f"(rc) : "f"(denF[r][c]));
            ob[(size_t)gi * TT + gj] = niF[r][c] * rc;   // coalesced across tx
            if (ti != tj)
                ob[(size_t)gj * TT + gi] = njF[r][c] * rc;   // mirror
        }
    }
}

extern "C" void kernel_launch(void* const* d_in, const int* in_sizes, int n_in,
                              void* d_out, int out_size) {
    const float* x = (const float*)d_in[0];    // (8,512,64)
    const float* W = (const float*)d_in[1];    // (64,64)
    const float* bias = (const float*)d_in[2]; // (64,)
    float* out = (float*)d_out;                // (8,512,512)

    v_kernel<<<(BB * TT) / 32, 256>>>(x, W, bias);
    rbf_kernel<<<dim3(NPAIR, BB), 256>>>(out);
}